// round 12
// baseline (speedup 1.0000x reference)
#include <cuda_runtime.h>
#include <cuda_bf16.h>
#include <cstdint>

#define SEQ 2048
#define DIM 64
#define BATCH 8
#define BM  64
#define TN  128
#define NT  (SEQ / TN)
#define FRAG_TILE_BYTES 16384   // 8 keygroups x 4 frag-blocks x 32 lanes x 16B

// __device__ scratch (allowed; no allocation)
__device__ char     g_Kf [BATCH * NT * FRAG_TILE_BYTES];  // K fragment-major (2 MB)
__device__ char     g_Vf [BATCH * NT * FRAG_TILE_BYTES];  // V fragment-major (2 MB)
__device__ uint2    g_k2i[BATCH * NT * 64];               // interleaved (k2[key],k2[key+8]) bf16x2 pairs
__device__ float    g_tcs[BATCH * NT * DIM];              // per-tile V colsums

#define ONES_BF16X2 0x3F803F80u
#define OB_ST 66

__device__ __forceinline__ void mma_bf16(float* c, const uint32_t* a, uint32_t b0, uint32_t b1) {
    asm("mma.sync.aligned.m16n8k16.row.col.f32.bf16.bf16.f32 "
        "{%0,%1,%2,%3}, {%4,%5,%6,%7}, {%8,%9}, {%0,%1,%2,%3};"
        : "+f"(c[0]), "+f"(c[1]), "+f"(c[2]), "+f"(c[3])
        : "r"(a[0]), "r"(a[1]), "r"(a[2]), "r"(a[3]), "r"(b0), "r"(b1));
}
__device__ __forceinline__ void mma_bf16_k8(float* c, uint32_t a0, uint32_t a1, uint32_t b0) {
    asm("mma.sync.aligned.m16n8k8.row.col.f32.bf16.bf16.f32 "
        "{%0,%1,%2,%3}, {%4,%5}, {%6}, {%0,%1,%2,%3};"
        : "+f"(c[0]), "+f"(c[1]), "+f"(c[2]), "+f"(c[3])
        : "r"(a0), "r"(a1), "r"(b0));
}
#define CVT_BF16X2(res, lo, hi) \
    asm("cvt.rn.bf16x2.f32 %0, %1, %2;" : "=r"(res) : "f"(hi), "f"(lo))

__device__ __forceinline__ float sqrt_approx(float x) {
    float r; asm("sqrt.approx.f32 %0, %1;" : "=f"(r) : "f"(x)); return r;
}
__device__ __forceinline__ float ex2_approx(float x) {
    float r; asm("ex2.approx.f32 %0, %1;" : "=f"(r) : "f"(x)); return r;
}
__device__ __forceinline__ uint32_t pack_bf16(float lo, float hi) {
    uint32_t r; CVT_BF16X2(r, lo, hi); return r;
}

// ============ prepass: fragment-major K/V bf16 images + interleaved k2 + V colsums ============
// smem (floats): Ks 8192 | Vs 8192 | part 2048 | k2tmp 128
#define PP_SMEM ((8192 + 8192 + 2048 + 128) * 4)
__global__ __launch_bounds__(512)
void gauss_prepass(const float* __restrict__ Kg, const float* __restrict__ V)
{
    extern __shared__ float psm[];
    float* Ks = psm;                        // [128][64]
    float* Vs = psm + 8192;                 // [128][64]
    float* part = psm + 16384;              // [512][4]
    uint32_t* k2tmp = (uint32_t*)(psm + 18432);  // [128]

    const int tile = blockIdx.x, b = blockIdx.y;
    const int tid = threadIdx.x;
    const int lane = tid & 31;
    const int ldc = tid & 15, ldr = tid >> 4;   // 0..31
    const size_t rowbase = (size_t)b * SEQ + tile * TN;

    float vc0 = 0.f, vc1 = 0.f, vc2 = 0.f, vc3 = 0.f;
    #pragma unroll
    for (int i = 0; i < 4; ++i) {
        int r = ldr + 32 * i;
        float4 kv = *(const float4*)(Kg + (rowbase + r) * DIM + ldc * 4);
        float4 vv = *(const float4*)(V  + (rowbase + r) * DIM + ldc * 4);
        *(float4*)(Ks + r * 64 + ldc * 4) = kv;
        *(float4*)(Vs + r * 64 + ldc * 4) = vv;
        vc0 += vv.x; vc1 += vv.y; vc2 += vv.z; vc3 += vv.w;
        float s = kv.x * kv.x + kv.y * kv.y + kv.z * kv.z + kv.w * kv.w;
        s += __shfl_xor_sync(0xffffffffu, s, 1);
        s += __shfl_xor_sync(0xffffffffu, s, 2);
        s += __shfl_xor_sync(0xffffffffu, s, 4);
        s += __shfl_xor_sync(0xffffffffu, s, 8);
        if ((lane & 15) == 0) {
            float h = __bfloat162float(__float2bfloat16(s));
            k2tmp[r] = pack_bf16(h, s - h);   // low=k2h, high=k2l
        }
    }
    ((float4*)part)[tid] = make_float4(vc0, vc1, vc2, vc3);
    __syncthreads();

    if (tid < 64) {
        int c = tid >> 2, k = tid & 3;
        float s = 0.f;
        #pragma unroll
        for (int j = 0; j < 32; ++j) s += part[(c + 16 * j) * 4 + k];
        g_tcs[((size_t)b * NT + tile) * DIM + tid] = s;
    }
    // interleaved k2 pairs: entry e = wn*32 + np*8 + g -> keys (wn*64+np*16+g, +8)
    if (tid < 64) {
        int key = ((tid >> 5) << 6) + (((tid >> 3) & 3) << 4) + (tid & 7);
        g_k2i[((size_t)b * NT + tile) * 64 + tid] = make_uint2(k2tmp[key], k2tmp[key + 8]);
    }

    char* kdst = g_Kf + ((size_t)b * NT + tile) * FRAG_TILE_BYTES;
    char* vdst = g_Vf + ((size_t)b * NT + tile) * FRAG_TILE_BYTES;

    // K fragments: widx = gidx*128 + kk*32 + lane
    #pragma unroll
    for (int i = 0; i < 2; ++i) {
        int widx = tid + 512 * i;
        int gidx = widx >> 7, kk = (widx >> 5) & 3, ln = widx & 31;
        int tt = ln & 3, gg = ln >> 2;
        const float* Kr0 = Ks + (gidx * 16 + gg) * 64 + kk * 16 + 2 * tt;
        const float* Kr8 = Kr0 + 8 * 64;
        uint4 u;
        u.x = pack_bf16(Kr0[0], Kr0[1]);
        u.y = pack_bf16(Kr0[8], Kr0[9]);
        u.z = pack_bf16(Kr8[0], Kr8[1]);
        u.w = pack_bf16(Kr8[8], Kr8[9]);
        *(uint4*)(kdst + widx * 16) = u;
    }
    // V fragments: widx = keygroup*128 + dg*32 + lane
    #pragma unroll
    for (int i = 0; i < 2; ++i) {
        int widx = tid + 512 * i;
        int kgp = widx >> 7, dg = (widx >> 5) & 3, ln = widx & 31;
        int tt = ln & 3, gg = ln >> 2;
        const float* Vt0 = Vs + (kgp * 16 + 2 * tt) * 64 + dg * 16 + gg;
        uint4 u;
        u.x = pack_bf16(Vt0[0],        Vt0[64]);
        u.y = pack_bf16(Vt0[8 * 64],   Vt0[9 * 64]);
        u.z = pack_bf16(Vt0[8],        Vt0[64 + 8]);
        u.w = pack_bf16(Vt0[8 * 64 + 8], Vt0[9 * 64 + 8]);
        *(uint4*)(vdst + widx * 16) = u;
    }
}

// ================== main kernel: barrier-free fragment streaming ==================
__global__ __launch_bounds__(256, 2)
void gauss_attn_mma(const float* __restrict__ Q, float* __restrict__ O)
{
    __shared__ float obf[BM * OB_ST];   // 16896 B
    __shared__ float rsS[128];
    __shared__ float svS[64];

    const int tid  = threadIdx.x;
    const int lane = tid & 31;
    const int wid  = tid >> 5;
    const int wm   = wid & 3;     // 16-row block
    const int wn   = wid >> 2;    // 64-key half
    const int g    = lane >> 2;
    const int t    = lane & 3;
    const int b    = blockIdx.y;
    const int m0   = blockIdx.x * BM;

    // ---- prologue: Q fragments (scaled by -2) + q2 + aug A-frag ----
    const int r0 = m0 + wm * 16 + g;
    const float* q0p = Q + ((size_t)b * SEQ + r0) * DIM;
    const float* q8p = q0p + 8 * DIM;

    float s0 = 0.f, s1 = 0.f;
    #pragma unroll
    for (int j = 0; j < 4; ++j) {
        float4 a = *(const float4*)(q0p + t * 16 + j * 4);
        float4 c = *(const float4*)(q8p + t * 16 + j * 4);
        s0 += a.x * a.x + a.y * a.y + a.z * a.z + a.w * a.w;
        s1 += c.x * c.x + c.y * c.y + c.z * c.z + c.w * c.w;
    }
    s0 += __shfl_xor_sync(0xffffffffu, s0, 1);
    s0 += __shfl_xor_sync(0xffffffffu, s0, 2);
    s1 += __shfl_xor_sync(0xffffffffu, s1, 1);
    s1 += __shfl_xor_sync(0xffffffffu, s1, 2);

    uint32_t aQ[4][4];
    #pragma unroll
    for (int kk = 0; kk < 4; ++kk) {
        float2 x0 = *(const float2*)(q0p + kk * 16 + 2 * t);
        float2 x1 = *(const float2*)(q8p + kk * 16 + 2 * t);
        float2 x2 = *(const float2*)(q0p + kk * 16 + 2 * t + 8);
        float2 x3 = *(const float2*)(q8p + kk * 16 + 2 * t + 8);
        aQ[kk][0] = pack_bf16(-2.f * x0.x, -2.f * x0.y);
        aQ[kk][1] = pack_bf16(-2.f * x1.x, -2.f * x1.y);
        aQ[kk][2] = pack_bf16(-2.f * x2.x, -2.f * x2.y);
        aQ[kk][3] = pack_bf16(-2.f * x3.x, -2.f * x3.y);
    }
    uint32_t aug0, aug1;
    {
        float h0 = __bfloat162float(__float2bfloat16(s0));
        float h1 = __bfloat162float(__float2bfloat16(s1));
        uint32_t p0 = pack_bf16(h0, s0 - h0);
        uint32_t p1 = pack_bf16(h1, s1 - h1);
        aug0 = (t == 0) ? p0 : ((t == 1) ? ONES_BF16X2 : 0u);
        aug1 = (t == 0) ? p1 : ((t == 1) ? ONES_BF16X2 : 0u);
    }
    if (tid < 64) {
        float s = 0.f;
        #pragma unroll
        for (int j = 0; j < NT; ++j) s += g_tcs[((size_t)b * NT + j) * DIM + tid];
        svS[tid] = s;
    }

    const char* __restrict__ kfb = g_Kf + (size_t)b * NT * FRAG_TILE_BYTES
                                   + (wn * 4) * 2048 + (size_t)lane * 16;
    const char* __restrict__ vfb = g_Vf + (size_t)b * NT * FRAG_TILE_BYTES
                                   + (wn * 4) * 2048 + (size_t)lane * 16;
    const uint2* __restrict__ k2ib = g_k2i + (size_t)b * NT * 64 + wn * 32 + g;

    float oacc[8][4] = {};
    float racc[4] = {};
    const float NL2E = -1.4426950408889634f;

    // ---- main loop: no smem, no barriers ----
    for (int it = 0; it < NT; ++it) {
        const char* kt = kfb + it * FRAG_TILE_BYTES;
        const char* vt = vfb + it * FRAG_TILE_BYTES;
        const uint2* k2t = k2ib + it * 64;

        #pragma unroll
        for (int np = 0; np < 4; ++np) {
            const int off = np * 2048;
            uint4 k0 = *(const uint4*)(kt + off);
            uint4 k1 = *(const uint4*)(kt + off + 512);
            uint4 k2w = *(const uint4*)(kt + off + 1024);
            uint4 k3 = *(const uint4*)(kt + off + 1536);
            uint2 kp = k2t[np * 8];
            uint32_t bA0 = (t == 0) ? ONES_BF16X2 : ((t == 1) ? kp.x : 0u);
            uint32_t bA1 = (t == 0) ? ONES_BF16X2 : ((t == 1) ? kp.y : 0u);

            // GEMM1 in two independent chains: sacc = aug + aQ0 + aQ1, tacc = aQ2 + aQ3
            float sacc[2][4] = {};
            float tacc[2][4] = {};
            mma_bf16_k8(sacc[0], aug0, aug1, bA0);
            mma_bf16_k8(sacc[1], aug0, aug1, bA1);
            mma_bf16(sacc[0], aQ[0], k0.x, k0.y);  mma_bf16(sacc[1], aQ[0], k0.z, k0.w);
            mma_bf16(tacc[0], aQ[2], k2w.x, k2w.y); mma_bf16(tacc[1], aQ[2], k2w.z, k2w.w);
            mma_bf16(sacc[0], aQ[1], k1.x, k1.y);  mma_bf16(sacc[1], aQ[1], k1.z, k1.w);
            mma_bf16(tacc[0], aQ[3], k3.x, k3.y);  mma_bf16(tacc[1], aQ[3], k3.z, k3.w);

            // V fragment loads here: K regs dead, latency hides under MUFU chain
            uint4 v0 = *(const uint4*)(vt + off);
            uint4 v1 = *(const uint4*)(vt + off + 512);
            uint4 v2 = *(const uint4*)(vt + off + 1024);
            uint4 v3 = *(const uint4*)(vt + off + 1536);

            // epilogue: d2 = sacc + tacc ; w = exp2(-log2e * sqrt(d2))
            uint32_t aP[4];
            #pragma unroll
            for (int njp = 0; njp < 2; ++njp) {
                float d0 = sacc[njp][0] + tacc[njp][0];
                float d1 = sacc[njp][1] + tacc[njp][1];
                float d2 = sacc[njp][2] + tacc[njp][2];
                float d3 = sacc[njp][3] + tacc[njp][3];
                float w0 = ex2_approx(sqrt_approx(d0) * NL2E);
                float w1 = ex2_approx(sqrt_approx(d1) * NL2E);
                float w2 = ex2_approx(sqrt_approx(d2) * NL2E);
                float w3 = ex2_approx(sqrt_approx(d3) * NL2E);
                aP[njp * 2 + 0] = pack_bf16(w0, w1);
                aP[njp * 2 + 1] = pack_bf16(w2, w3);
            }

            // GEMM2 + rowsum
            mma_bf16(oacc[0], aP, v0.x, v0.y);  mma_bf16(oacc[1], aP, v0.z, v0.w);
            mma_bf16(oacc[2], aP, v1.x, v1.y);  mma_bf16(oacc[3], aP, v1.z, v1.w);
            mma_bf16(oacc[4], aP, v2.x, v2.y);  mma_bf16(oacc[5], aP, v2.z, v2.w);
            mma_bf16(oacc[6], aP, v3.x, v3.y);  mma_bf16(oacc[7], aP, v3.z, v3.w);
            mma_bf16(racc, aP, ONES_BF16X2, ONES_BF16X2);
        }
    }

    // ================= finalization =================
    if ((lane & 3) == 0) {
        rsS[wn * 64 + wm * 16 + g]     = racc[0];
        rsS[wn * 64 + wm * 16 + g + 8] = racc[2];
    }
    if (wn == 0) {
        int row0 = wm * 16 + g;
        #pragma unroll
        for (int dj = 0; dj < 8; ++dj) {
            int col = dj * 8 + 2 * t;
            *(float2*)&obf[row0 * OB_ST + col] = make_float2(oacc[dj][0], oacc[dj][1]);
            *(float2*)&obf[(row0 + 8) * OB_ST + col] = make_float2(oacc[dj][2], oacc[dj][3]);
        }
    }
    __syncthreads();

    if (wn == 1) {
        int row0 = wm * 16 + g;
        float inv0 = 1.f / (2048.f + rsS[row0] + rsS[64 + row0]);
        float inv1 = 1.f / (2048.f + rsS[row0 + 8] + rsS[64 + row0 + 8]);
        #pragma unroll
        for (int dj = 0; dj < 8; ++dj) {
            int col = dj * 8 + 2 * t;
            float2 svp = *(const float2*)&svS[col];
            float2 o0 = *(const float2*)&obf[row0 * OB_ST + col];
            float2 o1 = *(const float2*)&obf[(row0 + 8) * OB_ST + col];
            float2 r0v = make_float2((oacc[dj][0] + o0.x + svp.x) * inv0,
                                     (oacc[dj][1] + o0.y + svp.y) * inv0);
            float2 r1v = make_float2((oacc[dj][2] + o1.x + svp.x) * inv1,
                                     (oacc[dj][3] + o1.y + svp.y) * inv1);
            *(float2*)&O[((size_t)b * SEQ + m0 + row0) * DIM + col] = r0v;
            *(float2*)&O[((size_t)b * SEQ + m0 + row0 + 8) * DIM + col] = r1v;
        }
    }
}

extern "C" void kernel_launch(void* const* d_in, const int* in_sizes, int n_in,
                              void* d_out, int out_size)
{
    const float* Q = (const float*)d_in[0];
    const float* K = (const float*)d_in[1];
    const float* V = (const float*)d_in[2];
    float* O = (float*)d_out;

    cudaFuncSetAttribute(gauss_prepass,
                         cudaFuncAttributeMaxDynamicSharedMemorySize, PP_SMEM);
    cudaFuncSetAttribute(gauss_attn_mma,
                         cudaFuncAttributePreferredSharedMemoryCarveout, 10);
    gauss_prepass<<<dim3(NT, BATCH), 512, PP_SMEM>>>(K, V);

    dim3 grid(SEQ / BM, BATCH);   // 32 x 8 = 256 CTAs, 2/SM
    gauss_attn_mma<<<grid, 256>>>(Q, O);
}

// round 13
// speedup vs baseline: 1.5521x; 1.5521x over previous
#include <cuda_runtime.h>
#include <cuda_bf16.h>
#include <cstdint>

#define SEQ 2048
#define DIM 64
#define BATCH 8
#define BM  64
#define TN  128
#define NT  (SEQ / TN)
#define FRAG_TILE_BYTES 16384   // 8 keygroups x 4 frag-blocks x 32 lanes x 16B

// __device__ scratch (allowed; no allocation)
__device__ char     g_Kf [BATCH * NT * FRAG_TILE_BYTES];  // K fragment-major (2 MB)
__device__ char     g_Vf [BATCH * NT * FRAG_TILE_BYTES];  // V fragment-major (2 MB)
__device__ uint2    g_k2i[BATCH * NT * 64];               // interleaved (k2[key],k2[key+8]) bf16x2 pairs
__device__ float    g_tcs[BATCH * NT * DIM];              // per-tile V colsums

#define ONES_BF16X2 0x3F803F80u
#define OB_ST 66

__device__ __forceinline__ void mma_bf16(float* c, const uint32_t* a, uint32_t b0, uint32_t b1) {
    asm("mma.sync.aligned.m16n8k16.row.col.f32.bf16.bf16.f32 "
        "{%0,%1,%2,%3}, {%4,%5,%6,%7}, {%8,%9}, {%0,%1,%2,%3};"
        : "+f"(c[0]), "+f"(c[1]), "+f"(c[2]), "+f"(c[3])
        : "r"(a[0]), "r"(a[1]), "r"(a[2]), "r"(a[3]), "r"(b0), "r"(b1));
}
__device__ __forceinline__ void mma_bf16_k8(float* c, uint32_t a0, uint32_t a1, uint32_t b0) {
    asm("mma.sync.aligned.m16n8k8.row.col.f32.bf16.bf16.f32 "
        "{%0,%1,%2,%3}, {%4,%5}, {%6}, {%0,%1,%2,%3};"
        : "+f"(c[0]), "+f"(c[1]), "+f"(c[2]), "+f"(c[3])
        : "r"(a0), "r"(a1), "r"(b0));
}
#define CVT_BF16X2(res, lo, hi) \
    asm("cvt.rn.bf16x2.f32 %0, %1, %2;" : "=r"(res) : "f"(hi), "f"(lo))

__device__ __forceinline__ float sqrt_approx(float x) {
    float r; asm("sqrt.approx.f32 %0, %1;" : "=f"(r) : "f"(x)); return r;
}
__device__ __forceinline__ float ex2_approx(float x) {
    float r; asm("ex2.approx.f32 %0, %1;" : "=f"(r) : "f"(x)); return r;
}
__device__ __forceinline__ uint32_t pack_bf16(float lo, float hi) {
    uint32_t r; CVT_BF16X2(r, lo, hi); return r;
}

// ============ prepass: fragment-major K/V bf16 images + interleaved k2 + V colsums ============
// smem (floats): Ks 8192 | Vs 8192 | part 2048 | k2tmp 128
#define PP_SMEM ((8192 + 8192 + 2048 + 128) * 4)
__global__ __launch_bounds__(512)
void gauss_prepass(const float* __restrict__ Kg, const float* __restrict__ V)
{
    extern __shared__ float psm[];
    float* Ks = psm;                        // [128][64]
    float* Vs = psm + 8192;                 // [128][64]
    float* part = psm + 16384;              // [512][4]
    uint32_t* k2tmp = (uint32_t*)(psm + 18432);  // [128]

    const int tile = blockIdx.x, b = blockIdx.y;
    const int tid = threadIdx.x;
    const int lane = tid & 31;
    const int ldc = tid & 15, ldr = tid >> 4;   // 0..31
    const size_t rowbase = (size_t)b * SEQ + tile * TN;

    float vc0 = 0.f, vc1 = 0.f, vc2 = 0.f, vc3 = 0.f;
    #pragma unroll
    for (int i = 0; i < 4; ++i) {
        int r = ldr + 32 * i;
        float4 kv = *(const float4*)(Kg + (rowbase + r) * DIM + ldc * 4);
        float4 vv = *(const float4*)(V  + (rowbase + r) * DIM + ldc * 4);
        *(float4*)(Ks + r * 64 + ldc * 4) = kv;
        *(float4*)(Vs + r * 64 + ldc * 4) = vv;
        vc0 += vv.x; vc1 += vv.y; vc2 += vv.z; vc3 += vv.w;
        float s = kv.x * kv.x + kv.y * kv.y + kv.z * kv.z + kv.w * kv.w;
        s += __shfl_xor_sync(0xffffffffu, s, 1);
        s += __shfl_xor_sync(0xffffffffu, s, 2);
        s += __shfl_xor_sync(0xffffffffu, s, 4);
        s += __shfl_xor_sync(0xffffffffu, s, 8);
        if ((lane & 15) == 0) {
            float h = __bfloat162float(__float2bfloat16(s));
            k2tmp[r] = pack_bf16(h, s - h);   // low=k2h, high=k2l
        }
    }
    ((float4*)part)[tid] = make_float4(vc0, vc1, vc2, vc3);
    __syncthreads();

    if (tid < 64) {
        int c = tid >> 2, k = tid & 3;
        float s = 0.f;
        #pragma unroll
        for (int j = 0; j < 32; ++j) s += part[(c + 16 * j) * 4 + k];
        g_tcs[((size_t)b * NT + tile) * DIM + tid] = s;
    }
    // interleaved k2 pairs: entry e = wn*32 + np*8 + g -> keys (wn*64+np*16+g, +8)
    if (tid < 64) {
        int key = ((tid >> 5) << 6) + (((tid >> 3) & 3) << 4) + (tid & 7);
        g_k2i[((size_t)b * NT + tile) * 64 + tid] = make_uint2(k2tmp[key], k2tmp[key + 8]);
    }

    char* kdst = g_Kf + ((size_t)b * NT + tile) * FRAG_TILE_BYTES;
    char* vdst = g_Vf + ((size_t)b * NT + tile) * FRAG_TILE_BYTES;

    // K fragments: widx = gidx*128 + kk*32 + lane
    #pragma unroll
    for (int i = 0; i < 2; ++i) {
        int widx = tid + 512 * i;
        int gidx = widx >> 7, kk = (widx >> 5) & 3, ln = widx & 31;
        int tt = ln & 3, gg = ln >> 2;
        const float* Kr0 = Ks + (gidx * 16 + gg) * 64 + kk * 16 + 2 * tt;
        const float* Kr8 = Kr0 + 8 * 64;
        uint4 u;
        u.x = pack_bf16(Kr0[0], Kr0[1]);
        u.y = pack_bf16(Kr0[8], Kr0[9]);
        u.z = pack_bf16(Kr8[0], Kr8[1]);
        u.w = pack_bf16(Kr8[8], Kr8[9]);
        *(uint4*)(kdst + widx * 16) = u;
    }
    // V fragments: widx = keygroup*128 + dg*32 + lane
    #pragma unroll
    for (int i = 0; i < 2; ++i) {
        int widx = tid + 512 * i;
        int kgp = widx >> 7, dg = (widx >> 5) & 3, ln = widx & 31;
        int tt = ln & 3, gg = ln >> 2;
        const float* Vt0 = Vs + (kgp * 16 + 2 * tt) * 64 + dg * 16 + gg;
        uint4 u;
        u.x = pack_bf16(Vt0[0],        Vt0[64]);
        u.y = pack_bf16(Vt0[8 * 64],   Vt0[9 * 64]);
        u.z = pack_bf16(Vt0[8],        Vt0[64 + 8]);
        u.w = pack_bf16(Vt0[8 * 64 + 8], Vt0[9 * 64 + 8]);
        *(uint4*)(vdst + widx * 16) = u;
    }
}

// ================== main kernel: barrier-free fragment streaming ==================
__global__ __launch_bounds__(256, 2)
void gauss_attn_mma(const float* __restrict__ Q, float* __restrict__ O)
{
    __shared__ float obf[BM * OB_ST];   // 16896 B
    __shared__ float rsS[128];
    __shared__ float svS[64];

    const int tid  = threadIdx.x;
    const int lane = tid & 31;
    const int wid  = tid >> 5;
    const int wm   = wid & 3;     // 16-row block
    const int wn   = wid >> 2;    // 64-key half
    const int g    = lane >> 2;
    const int t    = lane & 3;
    const int b    = blockIdx.y;
    const int m0   = blockIdx.x * BM;

    // ---- prologue: Q fragments (scaled by -2) + q2 + aug A-frag ----
    const int r0 = m0 + wm * 16 + g;
    const float* q0p = Q + ((size_t)b * SEQ + r0) * DIM;
    const float* q8p = q0p + 8 * DIM;

    float s0 = 0.f, s1 = 0.f;
    #pragma unroll
    for (int j = 0; j < 4; ++j) {
        float4 a = *(const float4*)(q0p + t * 16 + j * 4);
        float4 c = *(const float4*)(q8p + t * 16 + j * 4);
        s0 += a.x * a.x + a.y * a.y + a.z * a.z + a.w * a.w;
        s1 += c.x * c.x + c.y * c.y + c.z * c.z + c.w * c.w;
    }
    s0 += __shfl_xor_sync(0xffffffffu, s0, 1);
    s0 += __shfl_xor_sync(0xffffffffu, s0, 2);
    s1 += __shfl_xor_sync(0xffffffffu, s1, 1);
    s1 += __shfl_xor_sync(0xffffffffu, s1, 2);

    uint32_t aQ[4][4];
    #pragma unroll
    for (int kk = 0; kk < 4; ++kk) {
        float2 x0 = *(const float2*)(q0p + kk * 16 + 2 * t);
        float2 x1 = *(const float2*)(q8p + kk * 16 + 2 * t);
        float2 x2 = *(const float2*)(q0p + kk * 16 + 2 * t + 8);
        float2 x3 = *(const float2*)(q8p + kk * 16 + 2 * t + 8);
        aQ[kk][0] = pack_bf16(-2.f * x0.x, -2.f * x0.y);
        aQ[kk][1] = pack_bf16(-2.f * x1.x, -2.f * x1.y);
        aQ[kk][2] = pack_bf16(-2.f * x2.x, -2.f * x2.y);
        aQ[kk][3] = pack_bf16(-2.f * x3.x, -2.f * x3.y);
    }
    uint32_t aug0, aug1;
    {
        float h0 = __bfloat162float(__float2bfloat16(s0));
        float h1 = __bfloat162float(__float2bfloat16(s1));
        uint32_t p0 = pack_bf16(h0, s0 - h0);
        uint32_t p1 = pack_bf16(h1, s1 - h1);
        aug0 = (t == 0) ? p0 : ((t == 1) ? ONES_BF16X2 : 0u);
        aug1 = (t == 0) ? p1 : ((t == 1) ? ONES_BF16X2 : 0u);
    }
    if (tid < 64) {
        float s = 0.f;
        #pragma unroll
        for (int j = 0; j < NT; ++j) s += g_tcs[((size_t)b * NT + j) * DIM + tid];
        svS[tid] = s;
    }

    const char* __restrict__ kfb = g_Kf + (size_t)b * NT * FRAG_TILE_BYTES
                                   + (wn * 4) * 2048 + (size_t)lane * 16;
    const char* __restrict__ vfb = g_Vf + (size_t)b * NT * FRAG_TILE_BYTES
                                   + (wn * 4) * 2048 + (size_t)lane * 16;
    const uint2* __restrict__ k2ib = g_k2i + (size_t)b * NT * 64 + wn * 32 + g;

    float oacc[8][4] = {};
    float racc[4] = {};
    const float NL2E = -1.4426950408889634f;

    // ---- main loop: no smem, no barriers ----
    for (int it = 0; it < NT; ++it) {
        const char* kt = kfb + it * FRAG_TILE_BYTES;
        const char* vt = vfb + it * FRAG_TILE_BYTES;
        const uint2* k2t = k2ib + it * 64;

        #pragma unroll
        for (int np = 0; np < 4; ++np) {
            const int off = np * 2048;
            uint4 k0 = *(const uint4*)(kt + off);
            uint4 k1 = *(const uint4*)(kt + off + 512);
            uint4 k2w = *(const uint4*)(kt + off + 1024);
            uint4 k3 = *(const uint4*)(kt + off + 1536);
            uint2 kp = k2t[np * 8];
            uint32_t bA0 = (t == 0) ? ONES_BF16X2 : ((t == 1) ? kp.x : 0u);
            uint32_t bA1 = (t == 0) ? ONES_BF16X2 : ((t == 1) ? kp.y : 0u);

            // GEMM1 in two independent chains: sacc = aug + aQ0 + aQ1, tacc = aQ2 + aQ3
            float sacc[2][4] = {};
            float tacc[2][4] = {};
            mma_bf16_k8(sacc[0], aug0, aug1, bA0);
            mma_bf16_k8(sacc[1], aug0, aug1, bA1);
            mma_bf16(sacc[0], aQ[0], k0.x, k0.y);  mma_bf16(sacc[1], aQ[0], k0.z, k0.w);
            mma_bf16(tacc[0], aQ[2], k2w.x, k2w.y); mma_bf16(tacc[1], aQ[2], k2w.z, k2w.w);
            mma_bf16(sacc[0], aQ[1], k1.x, k1.y);  mma_bf16(sacc[1], aQ[1], k1.z, k1.w);
            mma_bf16(tacc[0], aQ[3], k3.x, k3.y);  mma_bf16(tacc[1], aQ[3], k3.z, k3.w);

            // V fragment loads here: K regs dead, latency hides under MUFU chain
            uint4 v0 = *(const uint4*)(vt + off);
            uint4 v1 = *(const uint4*)(vt + off + 512);
            uint4 v2 = *(const uint4*)(vt + off + 1024);
            uint4 v3 = *(const uint4*)(vt + off + 1536);

            // epilogue: d2 = sacc + tacc ; w = exp2(-log2e * sqrt(d2))
            uint32_t aP[4];
            #pragma unroll
            for (int njp = 0; njp < 2; ++njp) {
                float d0 = sacc[njp][0] + tacc[njp][0];
                float d1 = sacc[njp][1] + tacc[njp][1];
                float d2 = sacc[njp][2] + tacc[njp][2];
                float d3 = sacc[njp][3] + tacc[njp][3];
                float w0 = ex2_approx(sqrt_approx(d0) * NL2E);
                float w1 = ex2_approx(sqrt_approx(d1) * NL2E);
                float w2 = ex2_approx(sqrt_approx(d2) * NL2E);
                float w3 = ex2_approx(sqrt_approx(d3) * NL2E);
                aP[njp * 2 + 0] = pack_bf16(w0, w1);
                aP[njp * 2 + 1] = pack_bf16(w2, w3);
            }

            // GEMM2 + rowsum
            mma_bf16(oacc[0], aP, v0.x, v0.y);  mma_bf16(oacc[1], aP, v0.z, v0.w);
            mma_bf16(oacc[2], aP, v1.x, v1.y);  mma_bf16(oacc[3], aP, v1.z, v1.w);
            mma_bf16(oacc[4], aP, v2.x, v2.y);  mma_bf16(oacc[5], aP, v2.z, v2.w);
            mma_bf16(oacc[6], aP, v3.x, v3.y);  mma_bf16(oacc[7], aP, v3.z, v3.w);
            mma_bf16(racc, aP, ONES_BF16X2, ONES_BF16X2);
        }
    }

    // ================= finalization =================
    if ((lane & 3) == 0) {
        rsS[wn * 64 + wm * 16 + g]     = racc[0];
        rsS[wn * 64 + wm * 16 + g + 8] = racc[2];
    }
    if (wn == 0) {
        int row0 = wm * 16 + g;
        #pragma unroll
        for (int dj = 0; dj < 8; ++dj) {
            int col = dj * 8 + 2 * t;
            *(float2*)&obf[row0 * OB_ST + col] = make_float2(oacc[dj][0], oacc[dj][1]);
            *(float2*)&obf[(row0 + 8) * OB_ST + col] = make_float2(oacc[dj][2], oacc[dj][3]);
        }
    }
    __syncthreads();

    if (wn == 1) {
        int row0 = wm * 16 + g;
        float inv0 = 1.f / (2048.f + rsS[row0] + rsS[64 + row0]);
        float inv1 = 1.f / (2048.f + rsS[row0 + 8] + rsS[64 + row0 + 8]);
        #pragma unroll
        for (int dj = 0; dj < 8; ++dj) {
            int col = dj * 8 + 2 * t;
            float2 svp = *(const float2*)&svS[col];
            float2 o0 = *(const float2*)&obf[row0 * OB_ST + col];
            float2 o1 = *(const float2*)&obf[(row0 + 8) * OB_ST + col];
            float2 r0v = make_float2((oacc[dj][0] + o0.x + svp.x) * inv0,
                                     (oacc[dj][1] + o0.y + svp.y) * inv0);
            float2 r1v = make_float2((oacc[dj][2] + o1.x + svp.x) * inv1,
                                     (oacc[dj][3] + o1.y + svp.y) * inv1);
            *(float2*)&O[((size_t)b * SEQ + m0 + row0) * DIM + col] = r0v;
            *(float2*)&O[((size_t)b * SEQ + m0 + row0 + 8) * DIM + col] = r1v;
        }
    }
}

extern "C" void kernel_launch(void* const* d_in, const int* in_sizes, int n_in,
                              void* d_out, int out_size)
{
    const float* Q = (const float*)d_in[0];
    const float* K = (const float*)d_in[1];
    const float* V = (const float*)d_in[2];
    float* O = (float*)d_out;

    cudaFuncSetAttribute(gauss_prepass,
                         cudaFuncAttributeMaxDynamicSharedMemorySize, PP_SMEM);
    // NOTE: no PreferredSharedMemoryCarveout — round 12 showed it caps the smem
    // pool below 2 CTAs' worth and halves occupancy.
    gauss_prepass<<<dim3(NT, BATCH), 512, PP_SMEM>>>(K, V);

    dim3 grid(SEQ / BM, BATCH);   // 32 x 8 = 256 CTAs, 2/SM
    gauss_attn_mma<<<grid, 256>>>(Q, O);
}

// round 14
// speedup vs baseline: 1.5740x; 1.0141x over previous
#include <cuda_runtime.h>
#include <cuda_bf16.h>
#include <cstdint>

#define SEQ 2048
#define DIM 64
#define BATCH 8
#define BM  64
#define TN  128
#define NT  (SEQ / TN)
#define VF_TILE_BYTES 16384   // V: 8 keygroups x 4 frag-blocks x 32 lanes x 16B
#define KF_TILE_BYTES 8192    // K fp8: 8 keygroups x 2 chunks x 32 lanes x 16B

// __device__ scratch (allowed; no allocation)
__device__ char     g_Kf8[BATCH * NT * KF_TILE_BYTES];  // K e4m3 fragment-major (1 MB)
__device__ char     g_Vf [BATCH * NT * VF_TILE_BYTES];  // V bf16 fragment-major (2 MB)
__device__ uint2    g_k2i[BATCH * NT * 64];             // interleaved (k2[key],k2[key+8]) bf16x2 pairs
__device__ float    g_tcs[BATCH * NT * DIM];            // per-tile V colsums

#define ONES_BF16X2 0x3F803F80u
#define OB_ST 66

__device__ __forceinline__ void mma_bf16(float* c, const uint32_t* a, uint32_t b0, uint32_t b1) {
    asm("mma.sync.aligned.m16n8k16.row.col.f32.bf16.bf16.f32 "
        "{%0,%1,%2,%3}, {%4,%5,%6,%7}, {%8,%9}, {%0,%1,%2,%3};"
        : "+f"(c[0]), "+f"(c[1]), "+f"(c[2]), "+f"(c[3])
        : "r"(a[0]), "r"(a[1]), "r"(a[2]), "r"(a[3]), "r"(b0), "r"(b1));
}
__device__ __forceinline__ void mma_bf16_k8(float* c, uint32_t a0, uint32_t a1, uint32_t b0) {
    asm("mma.sync.aligned.m16n8k8.row.col.f32.bf16.bf16.f32 "
        "{%0,%1,%2,%3}, {%4,%5}, {%6}, {%0,%1,%2,%3};"
        : "+f"(c[0]), "+f"(c[1]), "+f"(c[2]), "+f"(c[3])
        : "r"(a0), "r"(a1), "r"(b0));
}
__device__ __forceinline__ void mma_fp8(float* c, const uint32_t* a, uint32_t b0, uint32_t b1) {
    asm("mma.sync.aligned.m16n8k32.row.col.f32.e4m3.e4m3.f32 "
        "{%0,%1,%2,%3}, {%4,%5,%6,%7}, {%8,%9}, {%0,%1,%2,%3};"
        : "+f"(c[0]), "+f"(c[1]), "+f"(c[2]), "+f"(c[3])
        : "r"(a[0]), "r"(a[1]), "r"(a[2]), "r"(a[3]), "r"(b0), "r"(b1));
}
#define CVT_BF16X2(res, lo, hi) \
    asm("cvt.rn.bf16x2.f32 %0, %1, %2;" : "=r"(res) : "f"(hi), "f"(lo))

__device__ __forceinline__ float sqrt_approx(float x) {
    float r; asm("sqrt.approx.f32 %0, %1;" : "=f"(r) : "f"(x)); return r;
}
__device__ __forceinline__ float ex2_approx(float x) {
    float r; asm("ex2.approx.f32 %0, %1;" : "=f"(r) : "f"(x)); return r;
}
__device__ __forceinline__ uint32_t pack_bf16(float lo, float hi) {
    uint32_t r; CVT_BF16X2(r, lo, hi); return r;
}
// bytes [f3 f2 f1 f0], byte0 = f0
__device__ __forceinline__ uint32_t pack_e4m3x4(float f0, float f1, float f2, float f3) {
    uint32_t r;
    asm("{ .reg .b16 lo, hi;\n\t"
        "cvt.rn.satfinite.e4m3x2.f32 lo, %2, %1;\n\t"
        "cvt.rn.satfinite.e4m3x2.f32 hi, %4, %3;\n\t"
        "mov.b32 %0, {lo, hi}; }"
        : "=r"(r) : "f"(f0), "f"(f1), "f"(f2), "f"(f3));
    return r;
}

// ============ prepass: K e4m3 frags + V bf16 frags + interleaved k2 + V colsums ============
// smem (floats): Ks 8192 | Vs 8192 | part 2048 | k2tmp 128
#define PP_SMEM ((8192 + 8192 + 2048 + 128) * 4)
__global__ __launch_bounds__(512)
void gauss_prepass(const float* __restrict__ Kg, const float* __restrict__ V)
{
    extern __shared__ float psm[];
    float* Ks = psm;                        // [128][64]
    float* Vs = psm + 8192;                 // [128][64]
    float* part = psm + 16384;              // [512][4]
    uint32_t* k2tmp = (uint32_t*)(psm + 18432);  // [128]

    const int tile = blockIdx.x, b = blockIdx.y;
    const int tid = threadIdx.x;
    const int lane = tid & 31;
    const int ldc = tid & 15, ldr = tid >> 4;   // 0..31
    const size_t rowbase = (size_t)b * SEQ + tile * TN;

    float vc0 = 0.f, vc1 = 0.f, vc2 = 0.f, vc3 = 0.f;
    #pragma unroll
    for (int i = 0; i < 4; ++i) {
        int r = ldr + 32 * i;
        float4 kv = *(const float4*)(Kg + (rowbase + r) * DIM + ldc * 4);
        float4 vv = *(const float4*)(V  + (rowbase + r) * DIM + ldc * 4);
        *(float4*)(Ks + r * 64 + ldc * 4) = kv;
        *(float4*)(Vs + r * 64 + ldc * 4) = vv;
        vc0 += vv.x; vc1 += vv.y; vc2 += vv.z; vc3 += vv.w;
        float s = kv.x * kv.x + kv.y * kv.y + kv.z * kv.z + kv.w * kv.w;
        s += __shfl_xor_sync(0xffffffffu, s, 1);
        s += __shfl_xor_sync(0xffffffffu, s, 2);
        s += __shfl_xor_sync(0xffffffffu, s, 4);
        s += __shfl_xor_sync(0xffffffffu, s, 8);
        if ((lane & 15) == 0) {
            float h = __bfloat162float(__float2bfloat16(s));
            k2tmp[r] = pack_bf16(h, s - h);   // low=k2h, high=k2l
        }
    }
    ((float4*)part)[tid] = make_float4(vc0, vc1, vc2, vc3);
    __syncthreads();

    if (tid < 64) {
        int c = tid >> 2, k = tid & 3;
        float s = 0.f;
        #pragma unroll
        for (int j = 0; j < 32; ++j) s += part[(c + 16 * j) * 4 + k];
        g_tcs[((size_t)b * NT + tile) * DIM + tid] = s;
    }
    // interleaved k2 pairs: entry e = wn*32 + np*8 + g -> keys (wn*64+np*16+g, +8)
    if (tid < 64) {
        int key = ((tid >> 5) << 6) + (((tid >> 3) & 3) << 4) + (tid & 7);
        g_k2i[((size_t)b * NT + tile) * 64 + tid] = make_uint2(k2tmp[key], k2tmp[key + 8]);
    }

    // K e4m3 fragments: one uint4 per thread. widx = npf*64 + c*32 + ln
    {
        char* kdst = g_Kf8 + ((size_t)b * NT + tile) * KF_TILE_BYTES;
        int npf = tid >> 6, c = (tid >> 5) & 1, ln = tid & 31;
        int tt = ln & 3, nl = ln >> 2;
        int n_lo = npf * 16 + nl;             // key row (and +8)
        int kb = 32 * c + 4 * tt;             // dim base
        const float* r0 = Ks + n_lo * 64 + kb;
        const float* r8 = r0 + 8 * 64;
        uint4 u;
        u.x = pack_e4m3x4(r0[0],  r0[1],  r0[2],  r0[3]);
        u.y = pack_e4m3x4(r0[16], r0[17], r0[18], r0[19]);
        u.z = pack_e4m3x4(r8[0],  r8[1],  r8[2],  r8[3]);
        u.w = pack_e4m3x4(r8[16], r8[17], r8[18], r8[19]);
        *(uint4*)(kdst + ((npf * 2 + c) * 32 + ln) * 16) = u;
    }

    // V bf16 fragments (unchanged layout): widx = keygroup*128 + dg*32 + lane
    char* vdst = g_Vf + ((size_t)b * NT + tile) * VF_TILE_BYTES;
    #pragma unroll
    for (int i = 0; i < 2; ++i) {
        int widx = tid + 512 * i;
        int kgp = widx >> 7, dg = (widx >> 5) & 3, ln = widx & 31;
        int tt = ln & 3, gg = ln >> 2;
        const float* Vt0 = Vs + (kgp * 16 + 2 * tt) * 64 + dg * 16 + gg;
        uint4 u;
        u.x = pack_bf16(Vt0[0],          Vt0[64]);
        u.y = pack_bf16(Vt0[8 * 64],     Vt0[9 * 64]);
        u.z = pack_bf16(Vt0[8],          Vt0[64 + 8]);
        u.w = pack_bf16(Vt0[8 * 64 + 8], Vt0[9 * 64 + 8]);
        *(uint4*)(vdst + widx * 16) = u;
    }
}

// ================== main kernel: barrier-free fragment streaming, fp8 GEMM1 ==================
__global__ __launch_bounds__(256, 2)
void gauss_attn_mma(const float* __restrict__ Q, float* __restrict__ O)
{
    __shared__ float obf[BM * OB_ST];   // 16896 B
    __shared__ float rsS[128];
    __shared__ float svS[64];

    const int tid  = threadIdx.x;
    const int lane = tid & 31;
    const int wid  = tid >> 5;
    const int wm   = wid & 3;     // 16-row block
    const int wn   = wid >> 2;    // 64-key half
    const int g    = lane >> 2;
    const int t    = lane & 3;
    const int b    = blockIdx.y;
    const int m0   = blockIdx.x * BM;

    // ---- prologue: Q fp8 A-frags (scaled by -2) + q2 + aug A-frag ----
    const int r0 = m0 + wm * 16 + g;
    const float* q0p = Q + ((size_t)b * SEQ + r0) * DIM;
    const float* q8p = q0p + 8 * DIM;

    float s0 = 0.f, s1 = 0.f;
    #pragma unroll
    for (int j = 0; j < 4; ++j) {
        float4 a = *(const float4*)(q0p + t * 16 + j * 4);
        float4 c = *(const float4*)(q8p + t * 16 + j * 4);
        s0 += a.x * a.x + a.y * a.y + a.z * a.z + a.w * a.w;
        s1 += c.x * c.x + c.y * c.y + c.z * c.z + c.w * c.w;
    }
    s0 += __shfl_xor_sync(0xffffffffu, s0, 1);
    s0 += __shfl_xor_sync(0xffffffffu, s0, 2);
    s1 += __shfl_xor_sync(0xffffffffu, s1, 1);
    s1 += __shfl_xor_sync(0xffffffffu, s1, 2);

    uint32_t aQ8[2][4];
    #pragma unroll
    for (int c = 0; c < 2; ++c) {
        float4 x0 = *(const float4*)(q0p + 32 * c + 4 * t);
        float4 x1 = *(const float4*)(q8p + 32 * c + 4 * t);
        float4 x2 = *(const float4*)(q0p + 32 * c + 4 * t + 16);
        float4 x3 = *(const float4*)(q8p + 32 * c + 4 * t + 16);
        aQ8[c][0] = pack_e4m3x4(-2.f * x0.x, -2.f * x0.y, -2.f * x0.z, -2.f * x0.w);
        aQ8[c][1] = pack_e4m3x4(-2.f * x1.x, -2.f * x1.y, -2.f * x1.z, -2.f * x1.w);
        aQ8[c][2] = pack_e4m3x4(-2.f * x2.x, -2.f * x2.y, -2.f * x2.z, -2.f * x2.w);
        aQ8[c][3] = pack_e4m3x4(-2.f * x3.x, -2.f * x3.y, -2.f * x3.z, -2.f * x3.w);
    }
    uint32_t aug0, aug1;
    {
        float h0 = __bfloat162float(__float2bfloat16(s0));
        float h1 = __bfloat162float(__float2bfloat16(s1));
        uint32_t p0 = pack_bf16(h0, s0 - h0);
        uint32_t p1 = pack_bf16(h1, s1 - h1);
        aug0 = (t == 0) ? p0 : ((t == 1) ? ONES_BF16X2 : 0u);
        aug1 = (t == 0) ? p1 : ((t == 1) ? ONES_BF16X2 : 0u);
    }
    if (tid < 64) {
        float s = 0.f;
        #pragma unroll
        for (int j = 0; j < NT; ++j) s += g_tcs[((size_t)b * NT + j) * DIM + tid];
        svS[tid] = s;
    }

    const char* __restrict__ kfb = g_Kf8 + (size_t)b * NT * KF_TILE_BYTES
                                   + wn * 4096 + (size_t)lane * 16;
    const char* __restrict__ vfb = g_Vf + (size_t)b * NT * VF_TILE_BYTES
                                   + (wn * 4) * 2048 + (size_t)lane * 16;
    const uint2* __restrict__ k2ib = g_k2i + (size_t)b * NT * 64 + wn * 32 + g;

    float oacc[8][4] = {};
    float racc[4] = {};
    const float NL2E = -1.4426950408889634f;

    // ---- main loop: no smem, no barriers ----
    for (int it = 0; it < NT; ++it) {
        const char* kt = kfb + it * KF_TILE_BYTES;
        const char* vt = vfb + it * VF_TILE_BYTES;
        const uint2* k2t = k2ib + it * 64;

        // preload the 4 k2 pairs for this tile (batched MLP)
        uint2 kpq[4];
        #pragma unroll
        for (int np = 0; np < 4; ++np) kpq[np] = k2t[np * 8];

        #pragma unroll
        for (int np = 0; np < 4; ++np) {
            uint4 ka = *(const uint4*)(kt + np * 1024);         // chunk 0 (dims 0-31)
            uint4 kb = *(const uint4*)(kt + np * 1024 + 512);   // chunk 1 (dims 32-63)
            uint32_t bA0 = (t == 0) ? ONES_BF16X2 : ((t == 1) ? kpq[np].x : 0u);
            uint32_t bA1 = (t == 0) ? ONES_BF16X2 : ((t == 1) ? kpq[np].y : 0u);

            // GEMM1 fp8 + aug: sacc = d2 = q2 + k2 - 2 q.k
            float sacc[2][4] = {};
            mma_bf16_k8(sacc[0], aug0, aug1, bA0);
            mma_bf16_k8(sacc[1], aug0, aug1, bA1);
            mma_fp8(sacc[0], aQ8[0], ka.x, ka.y);
            mma_fp8(sacc[1], aQ8[0], ka.z, ka.w);
            mma_fp8(sacc[0], aQ8[1], kb.x, kb.y);
            mma_fp8(sacc[1], aQ8[1], kb.z, kb.w);

            // V fragment loads: latency hides under MUFU chain below
            const int off = np * 2048;
            uint4 v0 = *(const uint4*)(vt + off);
            uint4 v1 = *(const uint4*)(vt + off + 512);
            uint4 v2 = *(const uint4*)(vt + off + 1024);
            uint4 v3 = *(const uint4*)(vt + off + 1536);

            // epilogue: w = exp2(-log2e * sqrt(d2))
            uint32_t aP[4];
            #pragma unroll
            for (int njp = 0; njp < 2; ++njp) {
                float w0 = ex2_approx(sqrt_approx(sacc[njp][0]) * NL2E);
                float w1 = ex2_approx(sqrt_approx(sacc[njp][1]) * NL2E);
                float w2 = ex2_approx(sqrt_approx(sacc[njp][2]) * NL2E);
                float w3 = ex2_approx(sqrt_approx(sacc[njp][3]) * NL2E);
                aP[njp * 2 + 0] = pack_bf16(w0, w1);
                aP[njp * 2 + 1] = pack_bf16(w2, w3);
            }

            // GEMM2 (bf16) + rowsum
            mma_bf16(oacc[0], aP, v0.x, v0.y);  mma_bf16(oacc[1], aP, v0.z, v0.w);
            mma_bf16(oacc[2], aP, v1.x, v1.y);  mma_bf16(oacc[3], aP, v1.z, v1.w);
            mma_bf16(oacc[4], aP, v2.x, v2.y);  mma_bf16(oacc[5], aP, v2.z, v2.w);
            mma_bf16(oacc[6], aP, v3.x, v3.y);  mma_bf16(oacc[7], aP, v3.z, v3.w);
            mma_bf16(racc, aP, ONES_BF16X2, ONES_BF16X2);
        }
    }

    // ================= finalization =================
    if ((lane & 3) == 0) {
        rsS[wn * 64 + wm * 16 + g]     = racc[0];
        rsS[wn * 64 + wm * 16 + g + 8] = racc[2];
    }
    if (wn == 0) {
        int row0 = wm * 16 + g;
        #pragma unroll
        for (int dj = 0; dj < 8; ++dj) {
            int col = dj * 8 + 2 * t;
            *(float2*)&obf[row0 * OB_ST + col] = make_float2(oacc[dj][0], oacc[dj][1]);
            *(float2*)&obf[(row0 + 8) * OB_ST + col] = make_float2(oacc[dj][2], oacc[dj][3]);
        }
    }
    __syncthreads();

    if (wn == 1) {
        int row0 = wm * 16 + g;
        float inv0 = 1.f / (2048.f + rsS[row0] + rsS[64 + row0]);
        float inv1 = 1.f / (2048.f + rsS[row0 + 8] + rsS[64 + row0 + 8]);
        #pragma unroll
        for (int dj = 0; dj < 8; ++dj) {
            int col = dj * 8 + 2 * t;
            float2 svp = *(const float2*)&svS[col];
            float2 o0 = *(const float2*)&obf[row0 * OB_ST + col];
            float2 o1 = *(const float2*)&obf[(row0 + 8) * OB_ST + col];
            float2 r0v = make_float2((oacc[dj][0] + o0.x + svp.x) * inv0,
                                     (oacc[dj][1] + o0.y + svp.y) * inv0);
            float2 r1v = make_float2((oacc[dj][2] + o1.x + svp.x) * inv1,
                                     (oacc[dj][3] + o1.y + svp.y) * inv1);
            *(float2*)&O[((size_t)b * SEQ + m0 + row0) * DIM + col] = r0v;
            *(float2*)&O[((size_t)b * SEQ + m0 + row0 + 8) * DIM + col] = r1v;
        }
    }
}

extern "C" void kernel_launch(void* const* d_in, const int* in_sizes, int n_in,
                              void* d_out, int out_size)
{
    const float* Q = (const float*)d_in[0];
    const float* K = (const float*)d_in[1];
    const float* V = (const float*)d_in[2];
    float* O = (float*)d_out;

    cudaFuncSetAttribute(gauss_prepass,
                         cudaFuncAttributeMaxDynamicSharedMemorySize, PP_SMEM);
    gauss_prepass<<<dim3(NT, BATCH), 512, PP_SMEM>>>(K, V);

    dim3 grid(SEQ / BM, BATCH);   // 32 x 8 = 256 CTAs, 2/SM
    gauss_attn_mma<<<grid, 256>>>(Q, O);
}